// round 3
// baseline (speedup 1.0000x reference)
#include <cuda_runtime.h>

#define NN 100000
#define NE 1600000
#define DIM 128
#define DV (DIM/4)   // 32 float4 per row

// ---- device scratch (allocations are forbidden; globals are the sanctioned path) ----
__device__ int   g_deg_in [NN];
__device__ int   g_deg_out[NN];
__device__ float g_ns[NN];           // rsqrt(out-degree incl self-loop)
__device__ float g_nd[NN];           // rsqrt(in-degree  incl self-loop)
__device__ int   g_off[NN + 1];      // CSR offsets by dst
__device__ int   g_cur[NN];
__device__ int   g_esrc[NE];         // src ids bucketed by dst
__device__ float g_A[NN * DIM];      // "hs" buffer (already *norm_src)
__device__ float g_B[NN * DIM];      // aggregated messages

// ---------------- preprocessing ----------------

__global__ void k_zero() {
    int i = blockIdx.x * blockDim.x + threadIdx.x;
    if (i < NN) { g_deg_in[i] = 0; g_deg_out[i] = 0; }
}

__global__ void k_count(const int* __restrict__ src, const int* __restrict__ dst) {
    int e = blockIdx.x * blockDim.x + threadIdx.x;
    if (e < NE) {
        atomicAdd(&g_deg_out[src[e]], 1);
        atomicAdd(&g_deg_in [dst[e]], 1);
    }
}

__global__ void k_norm() {
    int i = blockIdx.x * blockDim.x + threadIdx.x;
    if (i < NN) {
        g_ns[i] = rsqrtf((float)(g_deg_out[i] + 1));   // +1: self-loop
        g_nd[i] = rsqrtf((float)(g_deg_in [i] + 1));
    }
}

// single-block exclusive scan of g_deg_in -> g_off (and g_cur)
__global__ void k_scan() {
    __shared__ int wsum[32];
    __shared__ int carry;
    int tid = threadIdx.x, lane = tid & 31, wid = tid >> 5;
    if (tid == 0) carry = 0;
    __syncthreads();
    for (int base = 0; base < NN; base += 1024) {
        int i = base + tid;
        int v = (i < NN) ? g_deg_in[i] : 0;
        int x = v;
        #pragma unroll
        for (int o = 1; o < 32; o <<= 1) {
            int y = __shfl_up_sync(0xffffffffu, x, o);
            if (lane >= o) x += y;
        }
        if (lane == 31) wsum[wid] = x;
        __syncthreads();
        if (wid == 0) {
            int w = wsum[lane];
            #pragma unroll
            for (int o = 1; o < 32; o <<= 1) {
                int y = __shfl_up_sync(0xffffffffu, w, o);
                if (lane >= o) w += y;
            }
            wsum[lane] = w;
        }
        __syncthreads();
        int pre   = (wid > 0) ? wsum[wid - 1] : 0;
        int excl  = carry + pre + (x - v);
        if (i < NN) { g_off[i] = excl; g_cur[i] = excl; }
        int total = wsum[31];
        __syncthreads();
        if (tid == 0) carry += total;
        __syncthreads();
    }
    if (tid == 0) g_off[NN] = NE;
}

__global__ void k_fill(const int* __restrict__ src, const int* __restrict__ dst) {
    int e = blockIdx.x * blockDim.x + threadIdx.x;
    if (e < NE) {
        int p = atomicAdd(&g_cur[dst[e]], 1);
        g_esrc[p] = src[e];
    }
}

// ---------------- per-layer kernels ----------------

// A = inputs * norm_src   (only needed before layer 0; later layers fuse this
// into the GEMM epilogue)
__global__ void k_scale0(const float* __restrict__ in) {
    int i = blockIdx.x * blockDim.x + threadIdx.x;
    if (i >= NN * DV) return;
    float s = g_ns[i / DV];
    float4 v = ((const float4*)in)[i];
    v.x *= s; v.y *= s; v.z *= s; v.w *= s;
    ((float4*)g_A)[i] = v;
}

// B[node] = A[node] (self-loop) + sum_{e in in-edges(node)} A[src[e]]
// warp per node, float4 per lane, edge ids striped across lanes + shfl broadcast
__global__ void k_agg() {
    int lane = threadIdx.x & 31;
    int node = (blockIdx.x * blockDim.x + threadIdx.x) >> 5;
    if (node >= NN) return;
    const float4* __restrict__ A4 = (const float4*)g_A;
    float4 a = A4[node * DV + lane];
    float ax = a.x, ay = a.y, az = a.z, aw = a.w;
    int beg = g_off[node], end = g_off[node + 1];
    for (int base = beg; base < end; base += 32) {
        int cnt = min(32, end - base);
        int e = (lane < cnt) ? __ldg(&g_esrc[base + lane]) : 0;
        #pragma unroll 4
        for (int j = 0; j < cnt; j++) {
            int s = __shfl_sync(0xffffffffu, e, j);
            float4 v = __ldg(&A4[s * DV + lane]);
            ax += v.x; ay += v.y; az += v.z; aw += v.w;
        }
    }
    ((float4*)g_B)[node * DV + lane] = make_float4(ax, ay, az, aw);
}

// out_row = (B_row * norm_dst) @ W + b ; if fuse: out = relu(out)*norm_src -> g_A
//                                        else   : out -> out_ext (final layer)
// 64 rows x 128 cols per block, 256 threads, 8x(4-wide) register tile per thread
__global__ void k_gemm(const float* __restrict__ W, const float* __restrict__ bias,
                       float* __restrict__ out_ext, int fuse) {
    extern __shared__ float sm[];
    float*  Wsm  = sm;              // 128*128
    float*  Asm  = sm + DIM * DIM;  // 64*128
    float4* Wsm4 = (float4*)Wsm;
    float4* Asm4 = (float4*)Asm;

    int tid  = threadIdx.x;
    int row0 = blockIdx.x * 64;

    const float4* W4 = (const float4*)W;
    for (int i = tid; i < DIM * DIM / 4; i += 256) Wsm4[i] = W4[i];

    const float4* M4 = (const float4*)g_B;
    for (int i = tid; i < 64 * DV; i += 256) {
        int r = i / DV, c = i % DV, row = row0 + r;
        float4 v = make_float4(0.f, 0.f, 0.f, 0.f);
        if (row < NN) {
            v = M4[row * DV + c];
            float s = g_nd[row];
            v.x *= s; v.y *= s; v.z *= s; v.w *= s;
        }
        Asm4[i] = v;
    }
    __syncthreads();

    int tx = tid & 31;   // 4-col group
    int ty = tid >> 5;   // 8-row group
    float4 acc[8];
    #pragma unroll
    for (int r = 0; r < 8; r++) acc[r] = make_float4(0.f, 0.f, 0.f, 0.f);

    #pragma unroll 4
    for (int k = 0; k < DIM; k++) {
        float4 w = Wsm4[k * DV + tx];
        #pragma unroll
        for (int r = 0; r < 8; r++) {
            float a = Asm[(ty * 8 + r) * DIM + k];
            acc[r].x = fmaf(a, w.x, acc[r].x);
            acc[r].y = fmaf(a, w.y, acc[r].y);
            acc[r].z = fmaf(a, w.z, acc[r].z);
            acc[r].w = fmaf(a, w.w, acc[r].w);
        }
    }

    float4 b = ((const float4*)bias)[tx];
    float4* O4 = fuse ? (float4*)g_A : (float4*)out_ext;
    #pragma unroll
    for (int r = 0; r < 8; r++) {
        int row = row0 + ty * 8 + r;
        if (row >= NN) continue;
        float4 o = acc[r];
        o.x += b.x; o.y += b.y; o.z += b.z; o.w += b.w;
        if (fuse) {
            float s = g_ns[row];  // relu(h)*ns == relu(h*ns) since ns > 0
            o.x = fmaxf(o.x, 0.f) * s;
            o.y = fmaxf(o.y, 0.f) * s;
            o.z = fmaxf(o.z, 0.f) * s;
            o.w = fmaxf(o.w, 0.f) * s;
        }
        O4[row * DV + tx] = o;
    }
}

// ---------------- launch ----------------

extern "C" void kernel_launch(void* const* d_in, const int* in_sizes, int n_in,
                              void* d_out, int out_size) {
    const float* inp = (const float*)d_in[0];   // [NN, DIM]
    const float* Ws  = (const float*)d_in[1];   // [3, DIM, DIM]
    const float* bs  = (const float*)d_in[2];   // [3, DIM]
    const int*   src = (const int*)  d_in[3];   // [NE]
    const int*   dst = (const int*)  d_in[4];   // [NE]
    float* out = (float*)d_out;                 // [NN, DIM]

    const int GEMM_SMEM = (DIM * DIM + 64 * DIM) * (int)sizeof(float);  // 96 KB
    cudaFuncSetAttribute(k_gemm, cudaFuncAttributeMaxDynamicSharedMemorySize, GEMM_SMEM);

    int nb_n = (NN + 255) / 256;
    int nb_e = (NE + 255) / 256;

    // preprocessing: degrees, norms, CSR by dst
    k_zero <<<nb_n, 256>>>();
    k_count<<<nb_e, 256>>>(src, dst);
    k_norm <<<nb_n, 256>>>();
    k_scan <<<1, 1024>>>();
    k_fill <<<nb_e, 256>>>(src, dst);

    // layer 0 input scaling
    k_scale0<<<(NN * DV + 255) / 256, 256>>>(inp);

    int nb_agg  = (NN * 32 + 255) / 256;   // warp per node, 8 warps/block
    int nb_gemm = (NN + 63) / 64;

    for (int l = 0; l < 3; l++) {
        k_agg <<<nb_agg, 256>>>();
        k_gemm<<<nb_gemm, 256, GEMM_SMEM>>>(Ws + l * DIM * DIM, bs + l * DIM,
                                            out, (l < 2) ? 1 : 0);
    }
}

// round 5
// speedup vs baseline: 1.0920x; 1.0920x over previous
#include <cuda_runtime.h>

#define NN 100000
#define NE 1600000
#define DIM 128
#define DV (DIM/4)   // 32 float4 per row

// multi-block scan geometry: 256 threads x 8 elems = 2048 elems per block
#define SCAN_PER 2048
#define NBLK ((NN + SCAN_PER - 1) / SCAN_PER)   // 49

// ---- device scratch (allocations forbidden; globals are the sanctioned path) ----
__device__ int   g_deg_in [NN];
__device__ int   g_deg_out[NN];
__device__ float g_ns[NN];           // rsqrt(out-degree incl self-loop)
__device__ float g_nd[NN];           // rsqrt(in-degree  incl self-loop)
__device__ int   g_off[NN + 1];      // CSR offsets by dst
__device__ int   g_cur[NN];
__device__ int   g_esrc[NE];         // src ids bucketed by dst
__device__ int   g_bsum [NBLK];      // per-block degree sums
__device__ int   g_bbase[NBLK];      // exclusive scan of g_bsum
__device__ float g_A[NN * DIM];      // "hs" buffer (already *norm_src)
__device__ float g_B[NN * DIM];      // aggregated messages

// ---------------- preprocessing ----------------

__global__ void k_zero() {
    int i = blockIdx.x * blockDim.x + threadIdx.x;
    if (i < NN) { g_deg_in[i] = 0; g_deg_out[i] = 0; }
}

__global__ void k_count(const int* __restrict__ src, const int* __restrict__ dst) {
    int e = blockIdx.x * blockDim.x + threadIdx.x;
    if (e < NE) {
        atomicAdd(&g_deg_out[src[e]], 1);
        atomicAdd(&g_deg_in [dst[e]], 1);
    }
}

__global__ void k_norm() {
    int i = blockIdx.x * blockDim.x + threadIdx.x;
    if (i < NN) {
        g_ns[i] = rsqrtf((float)(g_deg_out[i] + 1));   // +1: self-loop
        g_nd[i] = rsqrtf((float)(g_deg_in [i] + 1));
    }
}

// phase 1: per-block sum of g_deg_in (2048 elems per block)
__global__ void k_bsum() {
    __shared__ int wsum[8];
    int tid = threadIdx.x, lane = tid & 31, wid = tid >> 5;
    int base = blockIdx.x * SCAN_PER + tid * 8;
    int t = 0;
    #pragma unroll
    for (int j = 0; j < 8; j++) {
        int i = base + j;
        t += (i < NN) ? g_deg_in[i] : 0;
    }
    #pragma unroll
    for (int o = 16; o > 0; o >>= 1) t += __shfl_down_sync(0xffffffffu, t, o);
    if (lane == 0) wsum[wid] = t;
    __syncthreads();
    if (tid == 0) {
        int s = 0;
        #pragma unroll
        for (int w = 0; w < 8; w++) s += wsum[w];
        g_bsum[blockIdx.x] = s;
    }
}

// phase 2: exclusive scan of NBLK (=49) block sums, one small block
__global__ void k_bscan() {
    __shared__ int sm[64];
    int tid = threadIdx.x;                       // 64 threads
    sm[tid] = (tid < NBLK) ? g_bsum[tid] : 0;
    __syncthreads();
    #pragma unroll
    for (int o = 1; o < 64; o <<= 1) {           // Hillis-Steele inclusive
        int v = (tid >= o) ? sm[tid - o] : 0;
        __syncthreads();
        sm[tid] += v;
        __syncthreads();
    }
    if (tid < NBLK) g_bbase[tid] = (tid > 0) ? sm[tid - 1] : 0;
    if (tid == 0) g_off[NN] = NE;
}

// phase 3: block-local exclusive scan + base -> g_off, g_cur
__global__ void k_lscan() {
    __shared__ int wsum[8];
    int tid = threadIdx.x, lane = tid & 31, wid = tid >> 5;
    int base = blockIdx.x * SCAN_PER + tid * 8;

    int v[8], t = 0;
    #pragma unroll
    for (int j = 0; j < 8; j++) {
        int i = base + j;
        v[j] = (i < NN) ? g_deg_in[i] : 0;
        t += v[j];
    }
    // warp exclusive scan over per-thread totals
    int x = t;
    #pragma unroll
    for (int o = 1; o < 32; o <<= 1) {
        int y = __shfl_up_sync(0xffffffffu, x, o);
        if (lane >= o) x += y;
    }
    if (lane == 31) wsum[wid] = x;
    int lane_excl = x - t;
    __syncthreads();
    if (tid == 0) {
        int s = 0;
        #pragma unroll
        for (int w = 0; w < 8; w++) { int a = wsum[w]; wsum[w] = s; s += a; }
    }
    __syncthreads();
    int run = g_bbase[blockIdx.x] + wsum[wid] + lane_excl;
    #pragma unroll
    for (int j = 0; j < 8; j++) {
        int i = base + j;
        if (i < NN) { g_off[i] = run; g_cur[i] = run; }
        run += v[j];
    }
}

__global__ void k_fill(const int* __restrict__ src, const int* __restrict__ dst) {
    int e = blockIdx.x * blockDim.x + threadIdx.x;
    if (e < NE) {
        int p = atomicAdd(&g_cur[dst[e]], 1);
        g_esrc[p] = src[e];
    }
}

// ---------------- per-layer kernels ----------------

// A = inputs * norm_src   (layer 0 only; later layers fuse into GEMM epilogue)
__global__ void k_scale0(const float* __restrict__ in) {
    int i = blockIdx.x * blockDim.x + threadIdx.x;
    if (i >= NN * DV) return;
    float s = g_ns[i / DV];
    float4 v = ((const float4*)in)[i];
    v.x *= s; v.y *= s; v.z *= s; v.w *= s;
    ((float4*)g_A)[i] = v;
}

// B[node] = A[node] (self-loop) + sum over in-edges of A[src]
// warp per node, float4 per lane, edge ids striped across lanes + shfl broadcast
__global__ void k_agg() {
    int lane = threadIdx.x & 31;
    int node = (blockIdx.x * blockDim.x + threadIdx.x) >> 5;
    if (node >= NN) return;
    const float4* __restrict__ A4 = (const float4*)g_A;
    float4 a = A4[node * DV + lane];
    float ax = a.x, ay = a.y, az = a.z, aw = a.w;
    int beg = g_off[node], end = g_off[node + 1];
    for (int base = beg; base < end; base += 32) {
        int cnt = min(32, end - base);
        int e = (lane < cnt) ? __ldg(&g_esrc[base + lane]) : 0;
        #pragma unroll 4
        for (int j = 0; j < cnt; j++) {
            int s = __shfl_sync(0xffffffffu, e, j);
            float4 v = __ldg(&A4[s * DV + lane]);
            ax += v.x; ay += v.y; az += v.z; aw += v.w;
        }
    }
    ((float4*)g_B)[node * DV + lane] = make_float4(ax, ay, az, aw);
}

// out_row = (B_row * norm_dst) @ W + b ; if fuse: out = relu(out)*norm_src -> g_A
//                                        else   : out -> out_ext (final layer)
// 64 rows x 128 cols per block, 256 threads, 8x(4-wide) register tile per thread
__global__ void k_gemm(const float* __restrict__ W, const float* __restrict__ bias,
                       float* __restrict__ out_ext, int fuse) {
    extern __shared__ float sm[];
    float*  Wsm  = sm;              // 128*128
    float*  Asm  = sm + DIM * DIM;  // 64*128
    float4* Wsm4 = (float4*)Wsm;
    float4* Asm4 = (float4*)Asm;

    int tid  = threadIdx.x;
    int row0 = blockIdx.x * 64;

    const float4* W4 = (const float4*)W;
    for (int i = tid; i < DIM * DIM / 4; i += 256) Wsm4[i] = W4[i];

    const float4* M4 = (const float4*)g_B;
    for (int i = tid; i < 64 * DV; i += 256) {
        int r = i / DV, c = i % DV, row = row0 + r;
        float4 v = make_float4(0.f, 0.f, 0.f, 0.f);
        if (row < NN) {
            v = M4[row * DV + c];
            float s = g_nd[row];
            v.x *= s; v.y *= s; v.z *= s; v.w *= s;
        }
        Asm4[i] = v;
    }
    __syncthreads();

    int tx = tid & 31;   // 4-col group
    int ty = tid >> 5;   // 8-row group
    float4 acc[8];
    #pragma unroll
    for (int r = 0; r < 8; r++) acc[r] = make_float4(0.f, 0.f, 0.f, 0.f);

    #pragma unroll 4
    for (int k = 0; k < DIM; k++) {
        float4 w = Wsm4[k * DV + tx];
        #pragma unroll
        for (int r = 0; r < 8; r++) {
            float a = Asm[(ty * 8 + r) * DIM + k];
            acc[r].x = fmaf(a, w.x, acc[r].x);
            acc[r].y = fmaf(a, w.y, acc[r].y);
            acc[r].z = fmaf(a, w.z, acc[r].z);
            acc[r].w = fmaf(a, w.w, acc[r].w);
        }
    }

    float4 b = ((const float4*)bias)[tx];
    float4* O4 = fuse ? (float4*)g_A : (float4*)out_ext;
    #pragma unroll
    for (int r = 0; r < 8; r++) {
        int row = row0 + ty * 8 + r;
        if (row >= NN) continue;
        float4 o = acc[r];
        o.x += b.x; o.y += b.y; o.z += b.z; o.w += b.w;
        if (fuse) {
            float s = g_ns[row];  // relu(h)*ns == relu(h*ns) since ns > 0
            o.x = fmaxf(o.x, 0.f) * s;
            o.y = fmaxf(o.y, 0.f) * s;
            o.z = fmaxf(o.z, 0.f) * s;
            o.w = fmaxf(o.w, 0.f) * s;
        }
        O4[row * DV + tx] = o;
    }
}

// ---------------- launch ----------------

extern "C" void kernel_launch(void* const* d_in, const int* in_sizes, int n_in,
                              void* d_out, int out_size) {
    const float* inp = (const float*)d_in[0];   // [NN, DIM]
    const float* Ws  = (const float*)d_in[1];   // [3, DIM, DIM]
    const float* bs  = (const float*)d_in[2];   // [3, DIM]
    const int*   src = (const int*)  d_in[3];   // [NE]
    const int*   dst = (const int*)  d_in[4];   // [NE]
    float* out = (float*)d_out;                 // [NN, DIM]

    const int GEMM_SMEM = (DIM * DIM + 64 * DIM) * (int)sizeof(float);  // 96 KB
    cudaFuncSetAttribute(k_gemm, cudaFuncAttributeMaxDynamicSharedMemorySize, GEMM_SMEM);

    int nb_n = (NN + 255) / 256;
    int nb_e = (NE + 255) / 256;

    // preprocessing: degrees, norms, CSR by dst (multi-block scan)
    k_zero <<<nb_n, 256>>>();
    k_count<<<nb_e, 256>>>(src, dst);
    k_norm <<<nb_n, 256>>>();
    k_bsum <<<NBLK, 256>>>();
    k_bscan<<<1, 64>>>();
    k_lscan<<<NBLK, 256>>>();
    k_fill <<<nb_e, 256>>>(src, dst);

    // layer 0 input scaling
    k_scale0<<<(NN * DV + 255) / 256, 256>>>(inp);

    int nb_agg  = (NN * 32 + 255) / 256;   // warp per node, 8 warps/block
    int nb_gemm = (NN + 63) / 64;

    for (int l = 0; l < 3; l++) {
        k_agg <<<nb_agg, 256>>>();
        k_gemm<<<nb_gemm, 256, GEMM_SMEM>>>(Ws + l * DIM * DIM, bs + l * DIM,
                                            out, (l < 2) ? 1 : 0);
    }
}

// round 6
// speedup vs baseline: 1.1911x; 1.0907x over previous
#include <cuda_runtime.h>

#define NN 100000
#define NE 1600000
#define DIM 128
#define DV (DIM/4)   // 32 float4 per row

// multi-block scan geometry: 256 threads x 8 elems = 2048 elems per block
#define SCAN_PER 2048
#define NBLK ((NN + SCAN_PER - 1) / SCAN_PER)   // 49

// smem row pitch (in 32-bit words) for the GEMM tiles: 128 + 8 pad
// -> W-fragment loads are provably conflict-free, A-fragment loads 2-way.
#define PITCH 136

// ---- device scratch (allocations forbidden; globals are the sanctioned path) ----
__device__ int   g_deg_in [NN];
__device__ int   g_deg_out[NN];
__device__ float g_ns[NN];           // rsqrt(out-degree incl self-loop)
__device__ float g_nd[NN];           // rsqrt(in-degree  incl self-loop)
__device__ int   g_off[NN + 1];      // CSR offsets by dst
__device__ int   g_cur[NN];
__device__ int   g_esrc[NE];         // src ids bucketed by dst
__device__ int   g_bsum [NBLK];
__device__ int   g_bbase[NBLK];
__device__ float g_A[NN * DIM];      // "hs" buffer (already *norm_src)
__device__ float g_B[NN * DIM];      // aggregated messages

// ---------------- preprocessing ----------------

__global__ void k_zero() {
    int i = blockIdx.x * blockDim.x + threadIdx.x;
    if (i < NN) { g_deg_in[i] = 0; g_deg_out[i] = 0; }
}

__global__ void k_count(const int* __restrict__ src, const int* __restrict__ dst) {
    int e = blockIdx.x * blockDim.x + threadIdx.x;
    if (e < NE) {
        atomicAdd(&g_deg_out[src[e]], 1);
        atomicAdd(&g_deg_in [dst[e]], 1);
    }
}

__global__ void k_norm() {
    int i = blockIdx.x * blockDim.x + threadIdx.x;
    if (i < NN) {
        g_ns[i] = rsqrtf((float)(g_deg_out[i] + 1));   // +1: self-loop
        g_nd[i] = rsqrtf((float)(g_deg_in [i] + 1));
    }
}

__global__ void k_bsum() {
    __shared__ int wsum[8];
    int tid = threadIdx.x, lane = tid & 31, wid = tid >> 5;
    int base = blockIdx.x * SCAN_PER + tid * 8;
    int t = 0;
    #pragma unroll
    for (int j = 0; j < 8; j++) {
        int i = base + j;
        t += (i < NN) ? g_deg_in[i] : 0;
    }
    #pragma unroll
    for (int o = 16; o > 0; o >>= 1) t += __shfl_down_sync(0xffffffffu, t, o);
    if (lane == 0) wsum[wid] = t;
    __syncthreads();
    if (tid == 0) {
        int s = 0;
        #pragma unroll
        for (int w = 0; w < 8; w++) s += wsum[w];
        g_bsum[blockIdx.x] = s;
    }
}

__global__ void k_bscan() {
    __shared__ int sm[64];
    int tid = threadIdx.x;                       // 64 threads
    sm[tid] = (tid < NBLK) ? g_bsum[tid] : 0;
    __syncthreads();
    #pragma unroll
    for (int o = 1; o < 64; o <<= 1) {
        int v = (tid >= o) ? sm[tid - o] : 0;
        __syncthreads();
        sm[tid] += v;
        __syncthreads();
    }
    if (tid < NBLK) g_bbase[tid] = (tid > 0) ? sm[tid - 1] : 0;
    if (tid == 0) g_off[NN] = NE;
}

__global__ void k_lscan() {
    __shared__ int wsum[8];
    int tid = threadIdx.x, lane = tid & 31, wid = tid >> 5;
    int base = blockIdx.x * SCAN_PER + tid * 8;

    int v[8], t = 0;
    #pragma unroll
    for (int j = 0; j < 8; j++) {
        int i = base + j;
        v[j] = (i < NN) ? g_deg_in[i] : 0;
        t += v[j];
    }
    int x = t;
    #pragma unroll
    for (int o = 1; o < 32; o <<= 1) {
        int y = __shfl_up_sync(0xffffffffu, x, o);
        if (lane >= o) x += y;
    }
    if (lane == 31) wsum[wid] = x;
    int lane_excl = x - t;
    __syncthreads();
    if (tid == 0) {
        int s = 0;
        #pragma unroll
        for (int w = 0; w < 8; w++) { int a = wsum[w]; wsum[w] = s; s += a; }
    }
    __syncthreads();
    int run = g_bbase[blockIdx.x] + wsum[wid] + lane_excl;
    #pragma unroll
    for (int j = 0; j < 8; j++) {
        int i = base + j;
        if (i < NN) { g_off[i] = run; g_cur[i] = run; }
        run += v[j];
    }
}

__global__ void k_fill(const int* __restrict__ src, const int* __restrict__ dst) {
    int e = blockIdx.x * blockDim.x + threadIdx.x;
    if (e < NE) {
        int p = atomicAdd(&g_cur[dst[e]], 1);
        g_esrc[p] = src[e];
    }
}

// ---------------- per-layer kernels ----------------

__global__ void k_scale0(const float* __restrict__ in) {
    int i = blockIdx.x * blockDim.x + threadIdx.x;
    if (i >= NN * DV) return;
    float s = g_ns[i / DV];
    float4 v = ((const float4*)in)[i];
    v.x *= s; v.y *= s; v.z *= s; v.w *= s;
    ((float4*)g_A)[i] = v;
}

// B[node] = A[node] (self-loop) + sum over in-edges of A[src]
__global__ void k_agg() {
    int lane = threadIdx.x & 31;
    int node = (blockIdx.x * blockDim.x + threadIdx.x) >> 5;
    if (node >= NN) return;
    const float4* __restrict__ A4 = (const float4*)g_A;
    float4 a = A4[node * DV + lane];
    float ax = a.x, ay = a.y, az = a.z, aw = a.w;
    int beg = g_off[node], end = g_off[node + 1];
    for (int base = beg; base < end; base += 32) {
        int cnt = min(32, end - base);
        int e = (lane < cnt) ? __ldg(&g_esrc[base + lane]) : 0;
        #pragma unroll 4
        for (int j = 0; j < cnt; j++) {
            int s = __shfl_sync(0xffffffffu, e, j);
            float4 v = __ldg(&A4[s * DV + lane]);
            ax += v.x; ay += v.y; az += v.z; aw += v.w;
        }
    }
    ((float4*)g_B)[node * DV + lane] = make_float4(ax, ay, az, aw);
}

// ---------------- tf32 tensor-core GEMM ----------------
// out_row = (B_row * norm_dst) @ W + b ; fuse: out = relu(out)*norm_src -> g_A
// block tile 128x128, 8 warps (2m x 4n) of 64x32, mma.sync.m16n8k8 tf32.

__device__ __forceinline__ unsigned f2tf32(float x) {
    unsigned u;
    asm("cvt.rna.tf32.f32 %0, %1;" : "=r"(u) : "f"(x));
    return u;
}

__global__ void __launch_bounds__(256, 1)
k_gemm(const float* __restrict__ W, const float* __restrict__ bias,
       float* __restrict__ out_ext, int fuse) {
    extern __shared__ unsigned sm[];
    unsigned* Asm = sm;                 // 128 x PITCH (tf32 bits)
    unsigned* Wsm = sm + DIM * PITCH;   // 128 x PITCH (tf32 bits), [k][n]

    int tid  = threadIdx.x;
    int row0 = blockIdx.x * 128;

    // stage W[k][n] -> tf32
    const float4* W4 = (const float4*)W;
    for (int i = tid; i < DIM * DV; i += 256) {
        int r = i >> 5, c4 = i & 31;
        float4 v = W4[i];
        uint4 u = make_uint4(f2tf32(v.x), f2tf32(v.y), f2tf32(v.z), f2tf32(v.w));
        *(uint4*)&Wsm[r * PITCH + c4 * 4] = u;
    }
    // stage A = g_B * nd -> tf32 (zeros past NN)
    const float4* M4 = (const float4*)g_B;
    for (int i = tid; i < 128 * DV; i += 256) {
        int r = i >> 5, c4 = i & 31, row = row0 + r;
        uint4 u = make_uint4(0u, 0u, 0u, 0u);
        if (row < NN) {
            float4 v = M4[row * DV + c4];
            float s = g_nd[row];
            u = make_uint4(f2tf32(v.x * s), f2tf32(v.y * s),
                           f2tf32(v.z * s), f2tf32(v.w * s));
        }
        *(uint4*)&Asm[r * PITCH + c4 * 4] = u;
    }
    __syncthreads();

    int lane = tid & 31, w = tid >> 5;
    int g = lane >> 2, t = lane & 3;        // groupID / threadID-in-group
    int m0w = (w & 1) * 64;                 // warp m origin (0 or 64)
    int n0w = (w >> 1) * 32;                // warp n origin (0,32,64,96)

    float acc[4][4][4];
    #pragma unroll
    for (int mt = 0; mt < 4; mt++)
        #pragma unroll
        for (int nt = 0; nt < 4; nt++)
            #pragma unroll
            for (int j = 0; j < 4; j++) acc[mt][nt][j] = 0.f;

    #pragma unroll 4
    for (int k0 = 0; k0 < DIM; k0 += 8) {
        unsigned a[4][4], b[4][2];
        #pragma unroll
        for (int mt = 0; mt < 4; mt++) {
            int r = m0w + mt * 16 + g;
            a[mt][0] = Asm[r * PITCH + k0 + t];
            a[mt][1] = Asm[(r + 8) * PITCH + k0 + t];
            a[mt][2] = Asm[r * PITCH + k0 + t + 4];
            a[mt][3] = Asm[(r + 8) * PITCH + k0 + t + 4];
        }
        #pragma unroll
        for (int nt = 0; nt < 4; nt++) {
            int c = n0w + nt * 8 + g;
            b[nt][0] = Wsm[(k0 + t) * PITCH + c];
            b[nt][1] = Wsm[(k0 + t + 4) * PITCH + c];
        }
        #pragma unroll
        for (int mt = 0; mt < 4; mt++)
            #pragma unroll
            for (int nt = 0; nt < 4; nt++) {
                asm volatile(
                    "mma.sync.aligned.m16n8k8.row.col.f32.tf32.tf32.f32 "
                    "{%0,%1,%2,%3}, {%4,%5,%6,%7}, {%8,%9}, {%0,%1,%2,%3};"
                    : "+f"(acc[mt][nt][0]), "+f"(acc[mt][nt][1]),
                      "+f"(acc[mt][nt][2]), "+f"(acc[mt][nt][3])
                    : "r"(a[mt][0]), "r"(a[mt][1]), "r"(a[mt][2]), "r"(a[mt][3]),
                      "r"(b[nt][0]), "r"(b[nt][1]));
            }
    }

    // epilogue: + bias, optional relu*norm_src, write float2 per fragment row
    float* O = fuse ? g_A : out_ext;
    #pragma unroll
    for (int mt = 0; mt < 4; mt++) {
        int rl = row0 + m0w + mt * 16 + g;
        int rh = rl + 8;
        float sl = 1.f, sh = 1.f;
        if (fuse) {
            if (rl < NN) sl = g_ns[rl];
            if (rh < NN) sh = g_ns[rh];
        }
        #pragma unroll
        for (int nt = 0; nt < 4; nt++) {
            int c = n0w + nt * 8 + 2 * t;
            float2 bb = *(const float2*)&bias[c];
            if (rl < NN) {
                float2 o;
                o.x = acc[mt][nt][0] + bb.x;
                o.y = acc[mt][nt][1] + bb.y;
                if (fuse) { o.x = fmaxf(o.x, 0.f) * sl; o.y = fmaxf(o.y, 0.f) * sl; }
                *(float2*)&O[rl * DIM + c] = o;
            }
            if (rh < NN) {
                float2 o;
                o.x = acc[mt][nt][2] + bb.x;
                o.y = acc[mt][nt][3] + bb.y;
                if (fuse) { o.x = fmaxf(o.x, 0.f) * sh; o.y = fmaxf(o.y, 0.f) * sh; }
                *(float2*)&O[rh * DIM + c] = o;
            }
        }
    }
}

// ---------------- launch ----------------

extern "C" void kernel_launch(void* const* d_in, const int* in_sizes, int n_in,
                              void* d_out, int out_size) {
    const float* inp = (const float*)d_in[0];   // [NN, DIM]
    const float* Ws  = (const float*)d_in[1];   // [3, DIM, DIM]
    const float* bs  = (const float*)d_in[2];   // [3, DIM]
    const int*   src = (const int*)  d_in[3];   // [NE]
    const int*   dst = (const int*)  d_in[4];   // [NE]
    float* out = (float*)d_out;                 // [NN, DIM]

    const int GEMM_SMEM = 2 * DIM * PITCH * (int)sizeof(unsigned);  // 139264 B
    cudaFuncSetAttribute(k_gemm, cudaFuncAttributeMaxDynamicSharedMemorySize, GEMM_SMEM);

    int nb_n = (NN + 255) / 256;
    int nb_e = (NE + 255) / 256;

    // preprocessing: degrees, norms, CSR by dst (multi-block scan)
    k_zero <<<nb_n, 256>>>();
    k_count<<<nb_e, 256>>>(src, dst);
    k_norm <<<nb_n, 256>>>();
    k_bsum <<<NBLK, 256>>>();
    k_bscan<<<1, 64>>>();
    k_lscan<<<NBLK, 256>>>();
    k_fill <<<nb_e, 256>>>(src, dst);

    // layer 0 input scaling
    k_scale0<<<(NN * DV + 255) / 256, 256>>>(inp);

    int nb_agg  = (NN * 32 + 255) / 256;   // warp per node
    int nb_gemm = (NN + 127) / 128;        // 782

    for (int l = 0; l < 3; l++) {
        k_agg <<<nb_agg, 256>>>();
        k_gemm<<<nb_gemm, 256, GEMM_SMEM>>>(Ws + l * DIM * DIM, bs + l * DIM,
                                            out, (l < 2) ? 1 : 0);
    }
}